// round 2
// baseline (speedup 1.0000x reference)
#include <cuda_runtime.h>

// PHM (Kronecker-factored) linear, fused two-stage fp32 kernel.
//
//   out[t, i*64+k] = sum_b sum_j sum_m A[b,i,j] * B[b,k,m] * x[t, j*64+m] + bias[i*64+k]
//
// Stage 1 (per b):  Y[t,j,k] = sum_m x[t,j,m] * B[b,k,m]
// Stage 2 (per b):  acc[t,i,k] += sum_j A[b,i,j] * Y[t,j,k]
//
// One CTA handles TOK=4 tokens with 256 threads. All operands staged in smem
// with conflict-free layouts; output accumulators live in registers.

#define TOK 4
#define XS_PITCH 68   // xsT row pitch (floats): (t, m, j) layout
#define YS_PITCH 68   // Ys  row pitch (floats): (t, j, k) layout
#define AS_PITCH 65   // AsT row pitch (floats): (j, i) layout

// smem layout (floats):
//   xsT : TOK*64*XS_PITCH  = 17408
//   Ys  : TOK*64*YS_PITCH  = 17408
//   Bs  : 64*64            =  4096   (k, m) natural
//   AsT : 64*AS_PITCH      =  4160   (j, i) transposed
// total = 43072 floats = 172288 bytes
#define SMEM_FLOATS (TOK*64*XS_PITCH + TOK*64*YS_PITCH + 64*64 + 64*AS_PITCH)

__global__ __launch_bounds__(256, 1)
void phm_fused_kernel(const float* __restrict__ x,
                      const float* __restrict__ A,
                      const float* __restrict__ B,
                      const float* __restrict__ bias,
                      float* __restrict__ out)
{
    extern __shared__ float sm[];
    float* xsT = sm;                              // [TOK][64(m)][XS_PITCH] holds x[t][j][m] at [t][m][j]
    float* Ys  = xsT + TOK * 64 * XS_PITCH;       // [TOK][64(j)][YS_PITCH]
    float* Bs  = Ys  + TOK * 64 * YS_PITCH;       // [64(k)][64(m)]
    float* AsT = Bs  + 64 * 64;                   // [64(j)][AS_PITCH] holds A[b][i][j] at [j][i]

    const int tid = threadIdx.x;
    const long t0 = (long)blockIdx.x * TOK;       // first token of this tile

    // ---- load x tile, transposed to (t, m, j) ----
    // global x layout: x[token][j*64 + m], m fastest.
    for (int idx = tid; idx < TOK * 64 * 64 / 4; idx += 256) {
        int e = idx * 4;                 // element offset within tile, m%4==0
        int t = e >> 12;                 // /4096
        int r = e & 4095;
        int j = r >> 6;
        int m = r & 63;
        float4 v = *(const float4*)(x + t0 * 4096 + e);
        float* base = xsT + t * 64 * XS_PITCH + j;
        base[(m + 0) * XS_PITCH] = v.x;
        base[(m + 1) * XS_PITCH] = v.y;
        base[(m + 2) * XS_PITCH] = v.z;
        base[(m + 3) * XS_PITCH] = v.w;
    }

    // persistent output accumulators: this thread owns out[t][i][0..63]
    float acc[64];
    #pragma unroll
    for (int k = 0; k < 64; k++) acc[k] = 0.0f;

    const int t = tid >> 6;       // token within tile (0..3); warp-uniform
    const int j = tid & 63;       // stage-1 row index (lane-consecutive)
    const int i = tid & 63;       // stage-2 output row index

    __syncthreads();

    for (int b = 0; b < 8; b++) {
        // ---- stage in B[b] (natural) and A[b] (transposed, pitch 65) ----
        const float* Bg = B + b * 4096;
        const float* Ag = A + b * 4096;
        #pragma unroll
        for (int idx = tid; idx < 1024; idx += 256) {
            *(float4*)(Bs + idx * 4) = *(const float4*)(Bg + idx * 4);
        }
        #pragma unroll
        for (int idx = tid; idx < 4096; idx += 256) {
            int ii = idx >> 6;
            int jj = idx & 63;
            AsT[jj * AS_PITCH + ii] = Ag[idx];   // conflict-free: banks (jj+ii)%32
        }
        __syncthreads();

        // ---- stage 1: Ys[t][j][k] = sum_m xsT[t][m][j] * Bs[k][m] ----
        {
            const float* xcol = xsT + t * 64 * XS_PITCH + j;   // stride XS_PITCH over m
            #pragma unroll
            for (int kh = 0; kh < 2; kh++) {
                float yacc[32];
                #pragma unroll
                for (int k = 0; k < 32; k++) yacc[k] = 0.0f;
                #pragma unroll 4
                for (int m = 0; m < 64; m++) {
                    float xv = xcol[m * XS_PITCH];             // lane-distinct j: conflict-free
                    const float* brow = Bs + m;                 // Bs[k][m], k varying: uniform addr -> broadcast
                    #pragma unroll
                    for (int k = 0; k < 32; k++)
                        yacc[k] += xv * brow[(kh * 32 + k) * 64];
                }
                float* yrow = Ys + (t * 64 + j) * YS_PITCH + kh * 32;
                #pragma unroll
                for (int k = 0; k < 32; k += 4) {
                    float4 v = make_float4(yacc[k], yacc[k + 1], yacc[k + 2], yacc[k + 3]);
                    *(float4*)(yrow + k) = v;                  // pitch 68: conflict-free STS.128
                }
            }
        }
        __syncthreads();

        // ---- stage 2: acc[k] += sum_j AsT[j][i] * Ys[t][j][k] ----
        {
            const float* yblk = Ys + t * 64 * YS_PITCH;
            #pragma unroll 2
            for (int jj = 0; jj < 64; jj++) {
                float av = AsT[jj * AS_PITCH + i];             // lane-consecutive i: conflict-free
                const float4* yrow = (const float4*)(yblk + jj * YS_PITCH);  // warp-uniform: broadcast
                #pragma unroll
                for (int kq = 0; kq < 16; kq++) {
                    float4 y4 = yrow[kq];
                    acc[kq * 4 + 0] += av * y4.x;
                    acc[kq * 4 + 1] += av * y4.y;
                    acc[kq * 4 + 2] += av * y4.z;
                    acc[kq * 4 + 3] += av * y4.w;
                }
            }
        }
        __syncthreads();
    }

    // ---- epilogue: add bias, store ----
    float* orow = out + (t0 + t) * 4096 + (long)i * 64;
    const float* brow = bias + i * 64;
    #pragma unroll
    for (int k = 0; k < 64; k += 4) {
        float4 bv = *(const float4*)(brow + k);
        float4 o;
        o.x = acc[k + 0] + bv.x;
        o.y = acc[k + 1] + bv.y;
        o.z = acc[k + 2] + bv.z;
        o.w = acc[k + 3] + bv.w;
        *(float4*)(orow + k) = o;
    }
}

extern "C" void kernel_launch(void* const* d_in, const int* in_sizes, int n_in,
                              void* d_out, int out_size)
{
    (void)in_sizes; (void)n_in; (void)out_size;
    const float* x    = (const float*)d_in[0];   // (8,2048,4096)
    const float* A    = (const float*)d_in[1];   // (8,64,64)
    const float* B    = (const float*)d_in[2];   // (8,64,64)
    const float* bias = (const float*)d_in[3];   // (4096,)
    float* out = (float*)d_out;                  // (8,2048,4096)

    const int TOKENS = 8 * 2048;                 // 16384
    const int smem_bytes = SMEM_FLOATS * (int)sizeof(float);   // 172288

    cudaFuncSetAttribute(phm_fused_kernel,
                         cudaFuncAttributeMaxDynamicSharedMemorySize, smem_bytes);

    dim3 grid(TOKENS / TOK);
    dim3 block(256);
    phm_fused_kernel<<<grid, block, smem_bytes>>>(x, A, B, bias, out);
}

// round 3
// speedup vs baseline: 2.9810x; 2.9810x over previous
#include <cuda_runtime.h>

// PHM (Kronecker-factored) linear — register-tiled, packed-fp32 (f32x2) fused kernel.
//
//   out[t, i*64+k] = sum_b sum_j sum_m A[b,i,j] * B[b,k,m] * x[t, j*64+m] + bias[i*64+k]
//
// Stage 1 (per b):  Y[t,j,k] = sum_m x[t,j,m] * B[b,k,m]     (64x64x64 GEMM / token)
// Stage 2 (per b):  acc[t,i,k] += sum_j A[b,i,j] * Y[t,j,k]  (accumulated in regs)
//
// One CTA = 4 tokens, 256 threads (64 threads/token in an 8x8 tile grid).
// Each thread computes an 8x8 output tile via outer products using
// fma.rn.f32x2 (SASS FFMA2) — 2 fp32 FMAs per instruction, bit-exact fp32.

#define TOK 4
#define XS_PITCH 68   // xsT [t][m][j] row pitch (16B-aligned rows)
#define YS_PITCH 64   // Ys  [t][j][k] row pitch
#define BS_PITCH 68   // BsT [m][k]    row pitch
#define AS_PITCH 68   // AsT [j][i]    row pitch

#define SMEM_FLOATS (TOK*64*XS_PITCH + TOK*64*YS_PITCH + 64*BS_PITCH + 64*AS_PITCH)

typedef unsigned long long u64t;

__device__ __forceinline__ u64t fma2(u64t a, u64t b, u64t c) {
    u64t d;
    asm("fma.rn.f32x2 %0, %1, %2, %3;" : "=l"(d) : "l"(a), "l"(b), "l"(c));
    return d;
}
__device__ __forceinline__ u64t dup2(float x) {
    u64t d;
    asm("mov.b64 %0, {%1, %1};" : "=l"(d) : "f"(x));
    return d;
}
__device__ __forceinline__ u64t add2(u64t a, u64t b) {
    u64t d;
    asm("add.rn.f32x2 %0, %1, %2;" : "=l"(d) : "l"(a), "l"(b));
    return d;
}

__global__ __launch_bounds__(256, 1)
void phm_v2_kernel(const float* __restrict__ x,
                   const float* __restrict__ A,
                   const float* __restrict__ B,
                   const float* __restrict__ bias,
                   float* __restrict__ out)
{
    extern __shared__ float sm[];
    float* xsT = sm;                              // [TOK][64(m)][XS_PITCH]: x[t][j][m] at [t][m][j]
    float* Ys  = xsT + TOK * 64 * XS_PITCH;       // [TOK][64(j)][YS_PITCH]
    float* BsT = Ys  + TOK * 64 * YS_PITCH;       // [64(m)][BS_PITCH]: B[b][k][m] at [m][k]
    float* AsT = BsT + 64 * BS_PITCH;             // [64(j)][AS_PITCH]: A[b][i][j] at [j][i]

    const int tid = threadIdx.x;
    const long t0 = (long)blockIdx.x * TOK;

    // ---- fill x tile transposed to (t, m, j), coalesced float4 global loads ----
    for (int idx = tid; idx < TOK * 64 * 64 / 4; idx += 256) {
        int e = idx * 4;
        int t = e >> 12;
        int r = e & 4095;
        int j = r >> 6;
        int m = r & 63;
        float4 v = *(const float4*)(x + t0 * 4096 + e);
        float* base = xsT + t * 64 * XS_PITCH + j;
        base[(m + 0) * XS_PITCH] = v.x;
        base[(m + 1) * XS_PITCH] = v.y;
        base[(m + 2) * XS_PITCH] = v.z;
        base[(m + 3) * XS_PITCH] = v.w;
    }

    const int t  = tid >> 6;       // token in tile (0..3)
    const int g  = tid & 63;       // thread within token group
    const int jt = g >> 3;         // row-tile index (8 rows), == it in stage 2
    const int kt = g & 7;          // col-tile index
    const int j0 = jt * 8;         // first row of tile (j in stage 1, i in stage 2)
    const int c0 = kt * 4;         // first col group (4 floats = 2 packed)
    const int c1 = 32 + kt * 4;    // second col group

    // persistent stage-2 accumulators: 8 rows x 8 cols as 8x4 packed f32x2
    u64t acc[8][4];
    #pragma unroll
    for (int r = 0; r < 8; r++)
        #pragma unroll
        for (int p = 0; p < 4; p++) acc[r][p] = 0ull;

    for (int b = 0; b < 8; b++) {
        // ---- stage B[b] -> BsT[m][k], A[b] -> AsT[j][i] (transposed) ----
        const float* Bg = B + b * 4096;
        const float* Ag = A + b * 4096;
        #pragma unroll
        for (int idx = tid; idx < 4096; idx += 256) {
            int row = idx >> 6;      // k (for B) / i (for A)
            int col = idx & 63;      // m (for B) / j (for A)
            BsT[col * BS_PITCH + row] = Bg[idx];
            AsT[col * AS_PITCH + row] = Ag[idx];
        }
        __syncthreads();   // (first iter: also covers the x fill)

        // ---- stage 1: Y[t][j0..j0+7][cols] = sum_m x[t][j][m] * B[k][m] ----
        {
            const float* xcol = xsT + t * 64 * XS_PITCH + j0;
            u64t y[8][4];
            #pragma unroll
            for (int r = 0; r < 8; r++)
                #pragma unroll
                for (int p = 0; p < 4; p++) y[r][p] = 0ull;

            #pragma unroll 4
            for (int m = 0; m < 64; m++) {
                // 8 x-values for this thread's rows (broadcast within phase)
                float4 xa = *(const float4*)(xcol + m * XS_PITCH);
                float4 xb = *(const float4*)(xcol + m * XS_PITCH + 4);
                u64t xd[8];
                xd[0] = dup2(xa.x); xd[1] = dup2(xa.y);
                xd[2] = dup2(xa.z); xd[3] = dup2(xa.w);
                xd[4] = dup2(xb.x); xd[5] = dup2(xb.y);
                xd[6] = dup2(xb.z); xd[7] = dup2(xb.w);
                // 8 B-values (2x ulonglong2 = 4 packed pairs), conflict-free
                const float* brow = BsT + m * BS_PITCH;
                ulonglong2 b0 = *(const ulonglong2*)(brow + c0);
                ulonglong2 b1 = *(const ulonglong2*)(brow + c1);
                #pragma unroll
                for (int r = 0; r < 8; r++) {
                    y[r][0] = fma2(xd[r], b0.x, y[r][0]);
                    y[r][1] = fma2(xd[r], b0.y, y[r][1]);
                    y[r][2] = fma2(xd[r], b1.x, y[r][2]);
                    y[r][3] = fma2(xd[r], b1.y, y[r][3]);
                }
            }
            // store Y tile (conflict-free: 8 distinct float4 span 32 banks/phase)
            #pragma unroll
            for (int r = 0; r < 8; r++) {
                float* yrow = Ys + (t * 64 + j0 + r) * YS_PITCH;
                ulonglong2 s0; s0.x = y[r][0]; s0.y = y[r][1];
                ulonglong2 s1; s1.x = y[r][2]; s1.y = y[r][3];
                *(ulonglong2*)(yrow + c0) = s0;
                *(ulonglong2*)(yrow + c1) = s1;
            }
        }
        __syncthreads();

        // ---- stage 2: acc[i0..i0+7][cols] += sum_j A[i][j] * Y[t][j][cols] ----
        {
            const float* yblk = Ys + t * 64 * YS_PITCH;
            #pragma unroll 4
            for (int j = 0; j < 64; j++) {
                const float* arow = AsT + j * AS_PITCH + j0;   // i0 == j0
                float4 aa = *(const float4*)(arow);
                float4 ab = *(const float4*)(arow + 4);
                u64t ad[8];
                ad[0] = dup2(aa.x); ad[1] = dup2(aa.y);
                ad[2] = dup2(aa.z); ad[3] = dup2(aa.w);
                ad[4] = dup2(ab.x); ad[5] = dup2(ab.y);
                ad[6] = dup2(ab.z); ad[7] = dup2(ab.w);
                const float* yrow = yblk + j * YS_PITCH;
                ulonglong2 y0 = *(const ulonglong2*)(yrow + c0);
                ulonglong2 y1 = *(const ulonglong2*)(yrow + c1);
                #pragma unroll
                for (int r = 0; r < 8; r++) {
                    acc[r][0] = fma2(ad[r], y0.x, acc[r][0]);
                    acc[r][1] = fma2(ad[r], y0.y, acc[r][1]);
                    acc[r][2] = fma2(ad[r], y1.x, acc[r][2]);
                    acc[r][3] = fma2(ad[r], y1.y, acc[r][3]);
                }
            }
        }
        __syncthreads();   // protect AsT/BsT/Ys before next b's staging
    }

    // ---- epilogue: add bias (packed), store coalesced 16B ----
    #pragma unroll
    for (int r = 0; r < 8; r++) {
        long row = (t0 + t) * 4096 + (long)(j0 + r) * 64;
        ulonglong2 bv0 = *(const ulonglong2*)(bias + (j0 + r) * 64 + c0);
        ulonglong2 bv1 = *(const ulonglong2*)(bias + (j0 + r) * 64 + c1);
        ulonglong2 o0, o1;
        o0.x = add2(acc[r][0], bv0.x);
        o0.y = add2(acc[r][1], bv0.y);
        o1.x = add2(acc[r][2], bv1.x);
        o1.y = add2(acc[r][3], bv1.y);
        *(ulonglong2*)(out + row + c0) = o0;
        *(ulonglong2*)(out + row + c1) = o1;
    }
}

extern "C" void kernel_launch(void* const* d_in, const int* in_sizes, int n_in,
                              void* d_out, int out_size)
{
    (void)in_sizes; (void)n_in; (void)out_size;
    const float* x    = (const float*)d_in[0];   // (8,2048,4096)
    const float* A    = (const float*)d_in[1];   // (8,64,64)
    const float* B    = (const float*)d_in[2];   // (8,64,64)
    const float* bias = (const float*)d_in[3];   // (4096,)
    float* out = (float*)d_out;                  // (8,2048,4096)

    const int TOKENS = 8 * 2048;
    const int smem_bytes = SMEM_FLOATS * (int)sizeof(float);   // 169984

    cudaFuncSetAttribute(phm_v2_kernel,
                         cudaFuncAttributeMaxDynamicSharedMemorySize, smem_bytes);

    phm_v2_kernel<<<TOKENS / TOK, 256, smem_bytes>>>(x, A, B, bias, out);
}

// round 7
// speedup vs baseline: 6.5163x; 2.1859x over previous
#include <cuda_runtime.h>
#include <cuda_fp16.h>
#include <cstdint>

// PHM (Kronecker) linear via warp-level mma.sync (HMMA, base sm_103 target)
// with 2-term fp16 splits (hi+lo, lo unscaled; A/B pre-scaled by 2^10).
//
//   Stage 1 (per b): D1[(t,j), k] = sum_m x[(t,j), m] * B[b][k][m]   M=256,N=64,K=64
//   Stage 2 (per b): D2[i, (t,k)] += sum_j A[b][i][j] * Y[j][(t,k)]  M=64,N=256,K=64
//
// Each stage GEMM = 3 HMMA passes: hi*hi + hi*lo + lo*hi (lo*lo dropped,
// ~2^-22 relative). D2 lives in registers across all 8 b. One CTA = 4 tokens,
// 512 threads (16 warps), 1 CTA/SM.

#define NTH 512
#define TOK 4

#define PX 72    // x tile pitch, halves  (rows (t,j): 256)
#define PW 72    // A/B tile pitch, halves (rows: 64)
#define PY 264   // Y tile pitch, halves  (rows j: 64, cols (t,k): 256)

// SMEM byte offsets
#define SM_XHI 0
#define SM_XLO 36864
#define SM_W   73728            // BHI | BLO | AHI | ALO, 9216 B each
#define SM_BHI (SM_W + 0)
#define SM_BLO (SM_W + 9216)
#define SM_AHI (SM_W + 18432)
#define SM_ALO (SM_W + 27648)
#define SM_YHI 110592
#define SM_YLO 144384
#define SM_TOTAL 178176

// Pre-split A/B images, per b: [BHI|BLO|AHI|ALO] each 64*72 halves, scaled 2^10.
__device__ __align__(16) __half g_w[8 * 4 * 64 * PW];

static __device__ __forceinline__ uint32_t smem_u32(const void* p) {
    uint32_t a;
    asm("{ .reg .u64 t; cvta.to.shared.u64 t, %1; cvt.u32.u64 %0, t; }" : "=r"(a) : "l"(p));
    return a;
}

#define LDSM_X4(r, addr)                                                      \
    asm volatile("ldmatrix.sync.aligned.m8n8.x4.shared.b16 {%0,%1,%2,%3}, [%4];" \
        : "=r"((r)[0]), "=r"((r)[1]), "=r"((r)[2]), "=r"((r)[3]) : "r"(addr))
#define LDSM_X2(r, addr)                                                      \
    asm volatile("ldmatrix.sync.aligned.m8n8.x2.shared.b16 {%0,%1}, [%2];"    \
        : "=r"((r)[0]), "=r"((r)[1]) : "r"(addr))
#define LDSM_X2T(r, addr)                                                     \
    asm volatile("ldmatrix.sync.aligned.m8n8.x2.trans.shared.b16 {%0,%1}, [%2];" \
        : "=r"((r)[0]), "=r"((r)[1]) : "r"(addr))

#define MMA16816(d, a, b)                                                     \
    asm volatile("mma.sync.aligned.m16n8k16.row.col.f32.f16.f16.f32 "         \
        "{%0,%1,%2,%3}, {%4,%5,%6,%7}, {%8,%9}, {%0,%1,%2,%3};"               \
        : "+f"((d)[0]), "+f"((d)[1]), "+f"((d)[2]), "+f"((d)[3])              \
        : "r"((a)[0]), "r"((a)[1]), "r"((a)[2]), "r"((a)[3]),                 \
          "r"((b)[0]), "r"((b)[1]))

// ---- prepass: split A/B (scaled 2^10) into fp16 hi/lo pitch-72 images ----
__global__ void phm_split_kernel(const float* __restrict__ A,
                                 const float* __restrict__ B)
{
    int idx = blockIdx.x * blockDim.x + threadIdx.x;   // 0..32767
    int b = idx >> 12, e = idx & 4095;
    int r = e >> 6, c = e & 63;
    __half* base = g_w + b * (4 * 64 * PW);
    float bv = B[idx] * 1024.0f;
    __half bh = __float2half_rn(bv);
    base[r * PW + c] = bh;
    base[4608 + r * PW + c] = __float2half_rn(bv - __half2float(bh));
    float av = A[idx] * 1024.0f;
    __half ah = __float2half_rn(av);
    base[9216 + r * PW + c] = ah;
    base[13824 + r * PW + c] = __float2half_rn(av - __half2float(ah));
}

__global__ __launch_bounds__(NTH, 1)
void phm_hmma_kernel(const float* __restrict__ x,
                     const float* __restrict__ bias,
                     float* __restrict__ out)
{
    extern __shared__ char sm[];
    const uint32_t smb = smem_u32(sm);

    const int tid  = threadIdx.x;
    const int wid  = tid >> 5;
    const int lane = tid & 31;
    const long t0  = (long)blockIdx.x * TOK;

    // ---- stage x (4 tokens) as fp16 hi/lo, rows (t,j)=(row), cols m, pitch 72 ----
    for (int idx = tid; idx < TOK * 4096 / 4; idx += NTH) {
        int e = idx * 4;
        int row = e >> 6;          // (t,j) 0..255
        int m = e & 63;
        float4 v = *(const float4*)(x + t0 * 4096 + e);
        __half2 h0 = __floats2half2_rn(v.x, v.y);
        __half2 h1 = __floats2half2_rn(v.z, v.w);
        __half2 l0 = __floats2half2_rn(v.x - __low2float(h0), v.y - __high2float(h0));
        __half2 l1 = __floats2half2_rn(v.z - __low2float(h1), v.w - __high2float(h1));
        int hoff = (row * PX + m) * 2;   // bytes
        *(__half2*)(sm + SM_XHI + hoff)     = h0;
        *(__half2*)(sm + SM_XHI + hoff + 4) = h1;
        *(__half2*)(sm + SM_XLO + hoff)     = l0;
        *(__half2*)(sm + SM_XLO + hoff + 4) = l1;
    }

    // ---- per-warp geometry ----
    // stage 1: warp strip rows [wid*16, wid*16+16) of M=256 ((t,j))
    const int s1row = wid * 16 + (lane & 15);                 // ldmatrix row
    const int jrow  = (wid & 3) * 16 + (lane >> 2);           // D1 row -> j
    const int tt1   = wid >> 2;                               // D1 row -> t
    // stage 2: warp (wid>>2) -> i strip, (wid&3) -> token
    const int istrip = (wid >> 2) * 16;
    const int tt2    = wid & 3;
    const int s2row  = istrip + (lane & 15);
    const int kc     = (lane & 3) * 2;

    // persistent stage-2 accumulators: 8 n-tiles x 4 f32
    float d2[8][4];
    #pragma unroll
    for (int n = 0; n < 8; n++)
        #pragma unroll
        for (int q = 0; q < 4; q++) d2[n][q] = 0.0f;

    for (int b = 0; b < 8; b++) {
        __syncthreads();   // prior stage-2 reads of W/Y done (iter 0: x stores pending)
        // ---- stage W[b]: straight 36864B copy (BHI|BLO|AHI|ALO) ----
        {
            const uint4* src = (const uint4*)(g_w + b * (4 * 64 * PW));
            #pragma unroll
            for (int idx = tid; idx < 2304; idx += NTH)
                *(uint4*)(sm + SM_W + idx * 16) = src[idx];
        }
        __syncthreads();

        // ---- stage 1: D1[(t,j), k] = x * B^T  (3 split passes) ----
        float d1[8][4];
        #pragma unroll
        for (int n = 0; n < 8; n++)
            #pragma unroll
            for (int q = 0; q < 4; q++) d1[n][q] = 0.0f;

        #pragma unroll
        for (int ch = 0; ch < 4; ch++) {
            uint32_t xh[4], xl[4];
            uint32_t xaddr = smb + ((s1row * PX) + ((lane >> 4) & 1) * 8 + ch * 16) * 2;
            LDSM_X4(xh, SM_XHI + xaddr);
            LDSM_X4(xl, SM_XLO + xaddr);
            #pragma unroll
            for (int n = 0; n < 8; n++) {
                uint32_t bh[2], bl[2];
                uint32_t baddr = smb +
                    (((n * 8 + (lane & 7)) * PW) + ch * 16 + ((lane >> 3) & 1) * 8) * 2;
                LDSM_X2(bh, SM_BHI + baddr);
                LDSM_X2(bl, SM_BLO + baddr);
                MMA16816(d1[n], xh, bh);
                MMA16816(d1[n], xh, bl);
                MMA16816(d1[n], xl, bh);
            }
        }

        // ---- convert + transpose: Y[j][(t,k)] fp16 hi/lo, half2 stores ----
        #pragma unroll
        for (int n = 0; n < 8; n++) {
            #pragma unroll
            for (int h = 0; h < 2; h++) {
                float c0 = d1[n][2 * h], c1 = d1[n][2 * h + 1];
                __half2 hi = __floats2half2_rn(c0, c1);
                __half2 lo = __floats2half2_rn(c0 - __low2float(hi),
                                               c1 - __high2float(hi));
                int yoff = ((jrow + 8 * h) * PY + tt1 * 64 + n * 8 + kc) * 2;
                *(__half2*)(sm + SM_YHI + yoff) = hi;
                *(__half2*)(sm + SM_YLO + yoff) = lo;
            }
        }
        __syncthreads();

        // ---- stage 2: D2[i, (t,k)] += A * Y  (3 split passes, accumulate) ----
        #pragma unroll
        for (int ch = 0; ch < 4; ch++) {
            uint32_t ah[4], al[4];
            uint32_t aaddr = smb + ((s2row * PW) + ((lane >> 4) & 1) * 8 + ch * 16) * 2;
            LDSM_X4(ah, SM_AHI + aaddr);
            LDSM_X4(al, SM_ALO + aaddr);
            #pragma unroll
            for (int n = 0; n < 8; n++) {
                uint32_t yh[2], yl[2];
                uint32_t yaddr = smb +
                    (((ch * 16 + (lane & 15)) * PY) + tt2 * 64 + n * 8) * 2;
                LDSM_X2T(yh, SM_YHI + yaddr);
                LDSM_X2T(yl, SM_YLO + yaddr);
                MMA16816(d2[n], ah, yh);
                MMA16816(d2[n], ah, yl);
                MMA16816(d2[n], al, yh);
            }
        }
    }

    // ---- epilogue: out[(t0+tt2), i*64+k] = D2 * 2^-20 + bias ----
    const float S = 0x1p-20f;
    float* obase = out + (t0 + tt2) * 4096;
    #pragma unroll
    for (int n = 0; n < 8; n++) {
        int k = n * 8 + kc;
        #pragma unroll
        for (int h = 0; h < 2; h++) {
            int i = istrip + (lane >> 2) + 8 * h;
            float2 bv = *(const float2*)(bias + i * 64 + k);
            float2 o;
            o.x = d2[n][2 * h]     * S + bv.x;
            o.y = d2[n][2 * h + 1] * S + bv.y;
            *(float2*)(obase + i * 64 + k) = o;
        }
    }
}

extern "C" void kernel_launch(void* const* d_in, const int* in_sizes, int n_in,
                              void* d_out, int out_size)
{
    (void)in_sizes; (void)n_in; (void)out_size;
    const float* x    = (const float*)d_in[0];   // (8,2048,4096)
    const float* A    = (const float*)d_in[1];   // (8,64,64)
    const float* B    = (const float*)d_in[2];   // (8,64,64)
    const float* bias = (const float*)d_in[3];   // (4096,)
    float* out = (float*)d_out;                  // (8,2048,4096)

    const int TOKENS = 8 * 2048;

    phm_split_kernel<<<32768 / 256, 256>>>(A, B);

    cudaFuncSetAttribute(phm_hmma_kernel,
                         cudaFuncAttributeMaxDynamicSharedMemorySize, SM_TOTAL);
    phm_hmma_kernel<<<TOKENS / TOK, NTH, SM_TOTAL>>>(x, bias, out);
}

// round 8
// speedup vs baseline: 8.2631x; 1.2681x over previous
#include <cuda_runtime.h>
#include <cuda_fp16.h>
#include <cstdint>

// PHM (Kronecker) linear via warp-level mma.sync (HMMA, base sm_103 target).
// Data operands (x, Y) use 2-term fp16 splits; weights A/B are plain fp16
// (scaled 2^10). Error ~2e-4 RMS, threshold 1e-3.
//
//   Stage 1 (per b): D1[(t,j), k] = sum_m x[(t,j), m] * B[b][k][m]   M=256,N=64,K=64
//                    2 passes: xhi*B + xlo*B
//   Stage 2 (per b): D2[i, (t,k)] += sum_j A[b][i][j] * Y[j][(t,k)]  M=64,N=256,K=64
//                    2 passes: A*Yhi + A*Ylo, accumulated in regs over b
//
// One CTA = 4 tokens, 512 threads (16 warps), 1 CTA/SM. W double-buffered.

#define NTH 512
#define TOK 4

#define PX 72    // x tile pitch, halves  (rows (t,j): 256)
#define PW 72    // A/B tile pitch, halves (rows: 64)
#define PY 264   // Y tile pitch, halves  (rows j: 64, cols (t,k): 256)

// SMEM byte offsets
#define SM_XHI 0
#define SM_XLO 36864
#define SM_W0  73728            // [BHI | AHI] per buffer, 9216 B each part
#define SM_WBUF_BYTES 18432
#define SM_AOFF 9216            // AHI offset within a W buffer
#define SM_YHI 110592
#define SM_YLO 144384
#define SM_TOTAL 178176

// Pre-split A/B images, per b: [BHI | AHI], each 64*PW halves, scaled 2^10.
__device__ __align__(16) __half g_w[8 * 2 * 64 * PW];

static __device__ __forceinline__ uint32_t smem_u32(const void* p) {
    uint32_t a;
    asm("{ .reg .u64 t; cvta.to.shared.u64 t, %1; cvt.u32.u64 %0, t; }" : "=r"(a) : "l"(p));
    return a;
}

#define LDSM_X4(r, addr)                                                      \
    asm volatile("ldmatrix.sync.aligned.m8n8.x4.shared.b16 {%0,%1,%2,%3}, [%4];" \
        : "=r"((r)[0]), "=r"((r)[1]), "=r"((r)[2]), "=r"((r)[3]) : "r"(addr))
#define LDSM_X4T(r, addr)                                                     \
    asm volatile("ldmatrix.sync.aligned.m8n8.x4.trans.shared.b16 {%0,%1,%2,%3}, [%4];" \
        : "=r"((r)[0]), "=r"((r)[1]), "=r"((r)[2]), "=r"((r)[3]) : "r"(addr))

#define MMA16816(d, a, b)                                                     \
    asm volatile("mma.sync.aligned.m16n8k16.row.col.f32.f16.f16.f32 "         \
        "{%0,%1,%2,%3}, {%4,%5,%6,%7}, {%8,%9}, {%0,%1,%2,%3};"               \
        : "+f"((d)[0]), "+f"((d)[1]), "+f"((d)[2]), "+f"((d)[3])              \
        : "r"((a)[0]), "r"((a)[1]), "r"((a)[2]), "r"((a)[3]),                 \
          "r"((b)[0]), "r"((b)[1]))

// ---- prepass: A/B (scaled 2^10) -> fp16 pitch-72 images ----
__global__ void phm_split_kernel(const float* __restrict__ A,
                                 const float* __restrict__ B)
{
    int idx = blockIdx.x * blockDim.x + threadIdx.x;   // 0..32767
    int b = idx >> 12, e = idx & 4095;
    int r = e >> 6, c = e & 63;
    __half* base = g_w + b * (2 * 64 * PW);
    base[r * PW + c]            = __float2half_rn(B[idx] * 1024.0f);
    base[64 * PW + r * PW + c]  = __float2half_rn(A[idx] * 1024.0f);
}

__global__ __launch_bounds__(NTH, 1)
void phm_hmma_kernel(const float* __restrict__ x,
                     const float* __restrict__ bias,
                     float* __restrict__ out)
{
    extern __shared__ char sm[];
    const uint32_t smb = smem_u32(sm);

    const int tid  = threadIdx.x;
    const int wid  = tid >> 5;
    const int lane = tid & 31;
    const long t0  = (long)blockIdx.x * TOK;

    // ---- stage x (4 tokens) as fp16 hi/lo, rows (t,j), cols m, pitch 72 ----
    for (int idx = tid; idx < TOK * 4096 / 4; idx += NTH) {
        int e = idx * 4;
        int row = e >> 6;          // (t,j) 0..255
        int m = e & 63;
        float4 v = *(const float4*)(x + t0 * 4096 + e);
        __half2 h0 = __floats2half2_rn(v.x, v.y);
        __half2 h1 = __floats2half2_rn(v.z, v.w);
        __half2 l0 = __floats2half2_rn(v.x - __low2float(h0), v.y - __high2float(h0));
        __half2 l1 = __floats2half2_rn(v.z - __low2float(h1), v.w - __high2float(h1));
        int hoff = (row * PX + m) * 2;
        *(__half2*)(sm + SM_XHI + hoff)     = h0;
        *(__half2*)(sm + SM_XHI + hoff + 4) = h1;
        *(__half2*)(sm + SM_XLO + hoff)     = l0;
        *(__half2*)(sm + SM_XLO + hoff + 4) = l1;
    }

    // ---- stage W[0] into buffer 0 ----
    {
        const uint4* src = (const uint4*)(g_w);
        #pragma unroll
        for (int idx = tid; idx < SM_WBUF_BYTES / 16; idx += NTH)
            *(uint4*)(sm + SM_W0 + idx * 16) = src[idx];
    }

    // ---- per-warp geometry ----
    const int s1row = wid * 16 + (lane & 15);                 // stage1 ldmatrix row
    const int jrow  = (wid & 3) * 16 + (lane >> 2);           // D1 row -> j
    const int tt1   = wid >> 2;                               // D1 row -> t
    const int istrip = (wid >> 2) * 16;                       // stage2 i strip
    const int tt2    = wid & 3;                               // stage2 token
    const int s2row  = istrip + (lane & 15);
    const int kc     = (lane & 3) * 2;

    // persistent stage-2 accumulators
    float d2[8][4];
    #pragma unroll
    for (int n = 0; n < 8; n++)
        #pragma unroll
        for (int q = 0; q < 4; q++) d2[n][q] = 0.0f;

    __syncthreads();   // x tiles + W[0] visible

    for (int b = 0; b < 8; b++) {
        const uint32_t wb = smb + SM_W0 + (b & 1) * SM_WBUF_BYTES;

        // ---- stage 1: D1[(t,j), k] = x * B^T  (xhi*B + xlo*B) ----
        float d1[8][4];
        #pragma unroll
        for (int n = 0; n < 8; n++)
            #pragma unroll
            for (int q = 0; q < 4; q++) d1[n][q] = 0.0f;

        #pragma unroll
        for (int ch = 0; ch < 4; ch++) {
            uint32_t xh[4], xl[4];
            uint32_t xaddr = smb + ((s1row * PX) + ((lane >> 4) & 1) * 8 + ch * 16) * 2;
            LDSM_X4(xh, SM_XHI + xaddr);
            LDSM_X4(xl, SM_XLO + xaddr);
            #pragma unroll
            for (int n2 = 0; n2 < 4; n2++) {
                uint32_t bb[4];   // two n-tiles' B fragments
                uint32_t baddr = wb +
                    (((n2 * 2 + (lane >> 4)) * 8 + (lane & 7)) * PW
                     + ch * 16 + ((lane >> 3) & 1) * 8) * 2;
                LDSM_X4(bb, baddr);
                MMA16816(d1[n2 * 2],     xh, bb);
                MMA16816(d1[n2 * 2],     xl, bb);
                MMA16816(d1[n2 * 2 + 1], xh, bb + 2);
                MMA16816(d1[n2 * 2 + 1], xl, bb + 2);
            }
        }

        // ---- convert + transpose: Y[j][(t,k)] fp16 hi/lo ----
        #pragma unroll
        for (int n = 0; n < 8; n++) {
            #pragma unroll
            for (int h = 0; h < 2; h++) {
                float c0 = d1[n][2 * h], c1 = d1[n][2 * h + 1];
                __half2 hi = __floats2half2_rn(c0, c1);
                __half2 lo = __floats2half2_rn(c0 - __low2float(hi),
                                               c1 - __high2float(hi));
                int yoff = ((jrow + 8 * h) * PY + tt1 * 64 + n * 8 + kc) * 2;
                *(__half2*)(sm + SM_YHI + yoff) = hi;
                *(__half2*)(sm + SM_YLO + yoff) = lo;
            }
        }
        __syncthreads();   // Y ready; prior W[b] B-reads done

        // ---- prefetch W[b+1] into the other buffer (overlaps stage-2 MMAs) ----
        if (b < 7) {
            const uint4* src = (const uint4*)(g_w + (b + 1) * (2 * 64 * PW));
            #pragma unroll
            for (int idx = tid; idx < SM_WBUF_BYTES / 16; idx += NTH)
                *(uint4*)(sm + SM_W0 + ((b + 1) & 1) * SM_WBUF_BYTES + idx * 16) = src[idx];
        }

        // ---- stage 2: D2[i, (t,k)] += A * Y  (A*Yhi + A*Ylo) ----
        #pragma unroll
        for (int ch = 0; ch < 4; ch++) {
            uint32_t ah[4];
            uint32_t aaddr = wb + SM_AOFF +
                ((s2row * PW) + ((lane >> 4) & 1) * 8 + ch * 16) * 2;
            LDSM_X4(ah, aaddr);
            #pragma unroll
            for (int n2 = 0; n2 < 4; n2++) {
                uint32_t yh[4], yl[4];
                uint32_t yaddr = smb +
                    ((ch * 16 + (lane & 15)) * PY
                     + tt2 * 64 + (n2 * 2 + (lane >> 4)) * 8) * 2;
                LDSM_X4T(yh, SM_YHI + yaddr);
                LDSM_X4T(yl, SM_YLO + yaddr);
                MMA16816(d2[n2 * 2],     ah, yh);
                MMA16816(d2[n2 * 2],     ah, yl);
                MMA16816(d2[n2 * 2 + 1], ah, yh + 2);
                MMA16816(d2[n2 * 2 + 1], ah, yl + 2);
            }
        }
        __syncthreads();   // Y safe to overwrite next b; W[b+1] visible
    }

    // ---- epilogue: out[(t0+tt2), i*64+k] = D2 * 2^-20 + bias ----
    const float S = 0x1p-20f;
    float* obase = out + (t0 + tt2) * 4096;
    #pragma unroll
    for (int n = 0; n < 8; n++) {
        int k = n * 8 + kc;
        #pragma unroll
        for (int h = 0; h < 2; h++) {
            int i = istrip + (lane >> 2) + 8 * h;
            float2 bv = *(const float2*)(bias + i * 64 + k);
            float2 o;
            o.x = d2[n][2 * h]     * S + bv.x;
            o.y = d2[n][2 * h + 1] * S + bv.y;
            *(float2*)(obase + i * 64 + k) = o;
        }
    }
}

extern "C" void kernel_launch(void* const* d_in, const int* in_sizes, int n_in,
                              void* d_out, int out_size)
{
    (void)in_sizes; (void)n_in; (void)out_size;
    const float* x    = (const float*)d_in[0];   // (8,2048,4096)
    const float* A    = (const float*)d_in[1];   // (8,64,64)
    const float* B    = (const float*)d_in[2];   // (8,64,64)
    const float* bias = (const float*)d_in[3];   // (4096,)
    float* out = (float*)d_out;                  // (8,2048,4096)

    const int TOKENS = 8 * 2048;

    phm_split_kernel<<<32768 / 256, 256>>>(A, B);

    cudaFuncSetAttribute(phm_hmma_kernel,
                         cudaFuncAttributeMaxDynamicSharedMemorySize, SM_TOTAL);
    phm_hmma_kernel<<<TOKENS / TOK, NTH, SM_TOTAL>>>(x, bias, out);
}

// round 9
// speedup vs baseline: 8.4750x; 1.0256x over previous
#include <cuda_runtime.h>
#include <cuda_fp16.h>
#include <cstdint>

// PHM (Kronecker) linear via warp-level mma.sync (HMMA), pure fp16 operands
// (x, B, Y, A all fp16; fp32 accumulation). Weights pre-scaled by 2^10,
// output rescaled by exact 2^-20. Measured-calibrated error ~4e-4 vs 1e-3.
//
//   Stage 1 (per b): D1[(t,j), k] = sum_m x[(t,j), m] * B[b][k][m]   M=256,N=64,K=64
//   Stage 2 (per b): D2[i, (t,k)] += sum_j A[b][i][j] * Y[j][(t,k)]  M=64,N=256,K=64
//
// One CTA = 4 tokens, 512 threads (16 warps), 2 CTAs/SM (105 KB smem).
// W (A,B fp16 images) double-buffered; D2 accumulated in registers over b.

#define NTH 512
#define TOK 4

#define PX 72    // x tile pitch, halves  (rows (t,j): 256)
#define PW 72    // A/B tile pitch, halves (rows: 64)
#define PY 264   // Y tile pitch, halves  (rows j: 64, cols (t,k): 256)

// SMEM byte offsets
#define SM_XHI 0                         // 256*72*2 = 36864
#define SM_W0  36864                     // 2 buffers x [BHI | AHI] (18432 each)
#define SM_WBUF_BYTES 18432
#define SM_AOFF 9216                     // AHI offset within a W buffer
#define SM_YHI 73728                     // 64*264*2 = 33792
#define SM_TOTAL 107520                  // 105 KB -> 2 CTAs/SM

// Pre-converted A/B images, per b: [BHI | AHI], each 64*PW halves, scaled 2^10.
__device__ __align__(16) __half g_w[8 * 2 * 64 * PW];

static __device__ __forceinline__ uint32_t smem_u32(const void* p) {
    uint32_t a;
    asm("{ .reg .u64 t; cvta.to.shared.u64 t, %1; cvt.u32.u64 %0, t; }" : "=r"(a) : "l"(p));
    return a;
}

#define LDSM_X4(r, addr)                                                      \
    asm volatile("ldmatrix.sync.aligned.m8n8.x4.shared.b16 {%0,%1,%2,%3}, [%4];" \
        : "=r"((r)[0]), "=r"((r)[1]), "=r"((r)[2]), "=r"((r)[3]) : "r"(addr))
#define LDSM_X4T(r, addr)                                                     \
    asm volatile("ldmatrix.sync.aligned.m8n8.x4.trans.shared.b16 {%0,%1,%2,%3}, [%4];" \
        : "=r"((r)[0]), "=r"((r)[1]), "=r"((r)[2]), "=r"((r)[3]) : "r"(addr))

#define MMA16816(d, a, b)                                                     \
    asm volatile("mma.sync.aligned.m16n8k16.row.col.f32.f16.f16.f32 "         \
        "{%0,%1,%2,%3}, {%4,%5,%6,%7}, {%8,%9}, {%0,%1,%2,%3};"               \
        : "+f"((d)[0]), "+f"((d)[1]), "+f"((d)[2]), "+f"((d)[3])              \
        : "r"((a)[0]), "r"((a)[1]), "r"((a)[2]), "r"((a)[3]),                 \
          "r"((b)[0]), "r"((b)[1]))

// ---- prepass: A/B (scaled 2^10) -> fp16 pitch-72 images ----
__global__ void phm_split_kernel(const float* __restrict__ A,
                                 const float* __restrict__ B)
{
    int idx = blockIdx.x * blockDim.x + threadIdx.x;   // 0..32767
    int b = idx >> 12, e = idx & 4095;
    int r = e >> 6, c = e & 63;
    __half* base = g_w + b * (2 * 64 * PW);
    base[r * PW + c]           = __float2half_rn(B[idx] * 1024.0f);
    base[64 * PW + r * PW + c] = __float2half_rn(A[idx] * 1024.0f);
}

__global__ __launch_bounds__(NTH, 2)
void phm_hmma_kernel(const float* __restrict__ x,
                     const float* __restrict__ bias,
                     float* __restrict__ out)
{
    extern __shared__ char sm[];
    const uint32_t smb = smem_u32(sm);

    const int tid  = threadIdx.x;
    const int wid  = tid >> 5;
    const int lane = tid & 31;
    const long t0  = (long)blockIdx.x * TOK;

    // ---- stage x (4 tokens) as fp16, rows (t,j), cols m, pitch 72 ----
    for (int idx = tid; idx < TOK * 4096 / 4; idx += NTH) {
        int e = idx * 4;
        int row = e >> 6;          // (t,j) 0..255
        int m = e & 63;
        float4 v = *(const float4*)(x + t0 * 4096 + e);
        __half2 h0 = __floats2half2_rn(v.x, v.y);
        __half2 h1 = __floats2half2_rn(v.z, v.w);
        int hoff = (row * PX + m) * 2;
        *(__half2*)(sm + SM_XHI + hoff)     = h0;
        *(__half2*)(sm + SM_XHI + hoff + 4) = h1;
    }

    // ---- stage W[0] into buffer 0 ----
    {
        const uint4* src = (const uint4*)(g_w);
        #pragma unroll
        for (int idx = tid; idx < SM_WBUF_BYTES / 16; idx += NTH)
            *(uint4*)(sm + SM_W0 + idx * 16) = src[idx];
    }

    // ---- per-warp geometry ----
    const int s1row = wid * 16 + (lane & 15);                 // stage1 ldmatrix row
    const int jrow  = (wid & 3) * 16 + (lane >> 2);           // D1 row -> j
    const int tt1   = wid >> 2;                               // D1 row -> t
    const int istrip = (wid >> 2) * 16;                       // stage2 i strip
    const int tt2    = wid & 3;                               // stage2 token
    const int s2row  = istrip + (lane & 15);
    const int kc     = (lane & 3) * 2;

    // persistent stage-2 accumulators
    float d2[8][4];
    #pragma unroll
    for (int n = 0; n < 8; n++)
        #pragma unroll
        for (int q = 0; q < 4; q++) d2[n][q] = 0.0f;

    __syncthreads();   // x tiles + W[0] visible

    for (int b = 0; b < 8; b++) {
        const uint32_t wb = smb + SM_W0 + (b & 1) * SM_WBUF_BYTES;

        // ---- stage 1: D1[(t,j), k] = x * B^T ----
        float d1[8][4];
        #pragma unroll
        for (int n = 0; n < 8; n++)
            #pragma unroll
            for (int q = 0; q < 4; q++) d1[n][q] = 0.0f;

        #pragma unroll
        for (int ch = 0; ch < 4; ch++) {
            uint32_t xh[4];
            uint32_t xaddr = smb + ((s1row * PX) + ((lane >> 4) & 1) * 8 + ch * 16) * 2;
            LDSM_X4(xh, SM_XHI + xaddr);
            #pragma unroll
            for (int n2 = 0; n2 < 4; n2++) {
                uint32_t bb[4];   // two n-tiles' B fragments
                uint32_t baddr = wb +
                    (((n2 * 2 + (lane >> 4)) * 8 + (lane & 7)) * PW
                     + ch * 16 + ((lane >> 3) & 1) * 8) * 2;
                LDSM_X4(bb, baddr);
                MMA16816(d1[n2 * 2],     xh, bb);
                MMA16816(d1[n2 * 2 + 1], xh, bb + 2);
            }
        }

        // ---- convert + transpose: Y[j][(t,k)] fp16 ----
        #pragma unroll
        for (int n = 0; n < 8; n++) {
            #pragma unroll
            for (int h = 0; h < 2; h++) {
                __half2 hi = __floats2half2_rn(d1[n][2 * h], d1[n][2 * h + 1]);
                int yoff = ((jrow + 8 * h) * PY + tt1 * 64 + n * 8 + kc) * 2;
                *(__half2*)(sm + SM_YHI + yoff) = hi;
            }
        }
        __syncthreads();   // Y ready; prior W[b] B-reads done

        // ---- prefetch W[b+1] into the other buffer (overlaps stage-2 MMAs) ----
        if (b < 7) {
            const uint4* src = (const uint4*)(g_w + (b + 1) * (2 * 64 * PW));
            #pragma unroll
            for (int idx = tid; idx < SM_WBUF_BYTES / 16; idx += NTH)
                *(uint4*)(sm + SM_W0 + ((b + 1) & 1) * SM_WBUF_BYTES + idx * 16) = src[idx];
        }

        // ---- stage 2: D2[i, (t,k)] += A * Y ----
        #pragma unroll
        for (int ch = 0; ch < 4; ch++) {
            uint32_t ah[4];
            uint32_t aaddr = wb + SM_AOFF +
                ((s2row * PW) + ((lane >> 4) & 1) * 8 + ch * 16) * 2;
            LDSM_X4(ah, aaddr);
            #pragma unroll
            for (int n2 = 0; n2 < 4; n2++) {
                uint32_t yh[4];
                uint32_t yaddr = smb +
                    ((ch * 16 + (lane & 15)) * PY
                     + tt2 * 64 + (n2 * 2 + (lane >> 4)) * 8) * 2;
                LDSM_X4T(yh, SM_YHI + yaddr);
                MMA16816(d2[n2 * 2],     ah, yh);
                MMA16816(d2[n2 * 2 + 1], ah, yh + 2);
            }
        }
        __syncthreads();   // Y safe to overwrite next b; W[b+1] visible
    }

    // ---- epilogue: out[(t0+tt2), i*64+k] = D2 * 2^-20 + bias ----
    const float S = 0x1p-20f;
    float* obase = out + (t0 + tt2) * 4096;
    #pragma unroll
    for (int n = 0; n < 8; n++) {
        int k = n * 8 + kc;
        #pragma unroll
        for (int h = 0; h < 2; h++) {
            int i = istrip + (lane >> 2) + 8 * h;
            float2 bv = *(const float2*)(bias + i * 64 + k);
            float2 o;
            o.x = d2[n][2 * h]     * S + bv.x;
            o.y = d2[n][2 * h + 1] * S + bv.y;
            *(float2*)(obase + i * 64 + k) = o;
        }
    }
}

extern "C" void kernel_launch(void* const* d_in, const int* in_sizes, int n_in,
                              void* d_out, int out_size)
{
    (void)in_sizes; (void)n_in; (void)out_size;
    const float* x    = (const float*)d_in[0];   // (8,2048,4096)
    const float* A    = (const float*)d_in[1];   // (8,64,64)
    const float* B    = (const float*)d_in[2];   // (8,64,64)
    const float* bias = (const float*)d_in[3];   // (4096,)
    float* out = (float*)d_out;                  // (8,2048,4096)

    const int TOKENS = 8 * 2048;

    phm_split_kernel<<<32768 / 256, 256>>>(A, B);

    cudaFuncSetAttribute(phm_hmma_kernel,
                         cudaFuncAttributeMaxDynamicSharedMemorySize, SM_TOTAL);
    phm_hmma_kernel<<<TOKENS / TOK, NTH, SM_TOTAL>>>(x, bias, out);
}